// round 1
// baseline (speedup 1.0000x reference)
#include <cuda_runtime.h>
#include <math.h>

#define BB 4
#define SS 2048
#define FF 64
#define DD 256
#define NROW (BB*SS)   // 8192

// ---------------- scratch (static __device__, no allocations) ----------------
__device__ float g_G[NROW*SS];      // 64 MB: x.x^T  (per batch block-diagonal usage)
__device__ float g_W[NROW*SS];      // 64 MB: first q.k^T, then overwritten with W
__device__ float g_q[NROW*FF];
__device__ float g_k[NROW*FF];
__device__ float g_sq[NROW];
__device__ float g_invn[NROW];
__device__ float4 g_stats[NROW];    // vmin, vmax, rowmax(score), softmax denom
__device__ float g_pe[NROW*FF];

// ---------------- kernel 1: q/k projection + per-row norms ----------------
__global__ void k_pre(const float* __restrict__ x,
                      const float* __restrict__ qW, const float* __restrict__ qb,
                      const float* __restrict__ kW, const float* __restrict__ kb) {
    __shared__ float xs[4][FF];
    __shared__ float red[256];
    int tid = threadIdx.x;
    int ty = tid >> 6, f = tid & 63;
    int row = blockIdx.x * 4 + ty;
    float xv = x[(size_t)row*FF + f];
    xs[ty][f] = xv;
    red[tid] = xv * xv;
    __syncthreads();
    #pragma unroll
    for (int o = 32; o >= 1; o >>= 1) {
        if (f < o) red[tid] += red[tid + o];
        __syncthreads();
    }
    float q = qb[f], k = kb[f];
    #pragma unroll
    for (int g = 0; g < FF; g++) {
        float xg = xs[ty][g];
        q = fmaf(xg, qW[g*FF + f], q);
        k = fmaf(xg, kW[g*FF + f], k);
    }
    g_q[(size_t)row*FF + f] = q;
    g_k[(size_t)row*FF + f] = k;
    if (f == 0) {
        float sq = red[ty*64];
        g_sq[row] = sq;
        g_invn[row] = 1.0f / fmaxf(sqrtf(sq), 1e-12f);
    }
}

// ---------------- kernel 2: G = x.x^T and SC = q.k^T, 64x64 tiles ----------------
__global__ void k_gemm1(const float* __restrict__ x) {
    __shared__ float Xs[32][68], Xt[32][68], Qs[32][68], Kt[32][68];
    int tid = threadIdx.x;
    int b = blockIdx.z;
    int s0 = blockIdx.y * 64, t0 = blockIdx.x * 64;
    const float* xb = x   + (size_t)b*SS*FF;
    const float* qb_ = g_q + (size_t)b*SS*FF;
    const float* kb_ = g_k + (size_t)b*SS*FF;
    int tx = tid & 15, ty = tid >> 4;
    float accG[4][4] = {{0}}, accC[4][4] = {{0}};
    for (int fc = 0; fc < FF; fc += 32) {
        __syncthreads();
        for (int l = tid; l < 64*32; l += 256) {
            int i = l >> 5, f = l & 31;
            Xs[f][i] = xb[(size_t)(s0+i)*FF + fc + f];
            Qs[f][i] = qb_[(size_t)(s0+i)*FF + fc + f];
            Xt[f][i] = xb[(size_t)(t0+i)*FF + fc + f];
            Kt[f][i] = kb_[(size_t)(t0+i)*FF + fc + f];
        }
        __syncthreads();
        #pragma unroll 8
        for (int f = 0; f < 32; f++) {
            float4 ax = *(const float4*)&Xs[f][ty*4];
            float4 aq = *(const float4*)&Qs[f][ty*4];
            float4 bx = *(const float4*)&Xt[f][tx*4];
            float4 bk = *(const float4*)&Kt[f][tx*4];
            float av[4] = {ax.x, ax.y, ax.z, ax.w};
            float qv[4] = {aq.x, aq.y, aq.z, aq.w};
            float bv[4] = {bx.x, bx.y, bx.z, bx.w};
            float kv[4] = {bk.x, bk.y, bk.z, bk.w};
            #pragma unroll
            for (int i = 0; i < 4; i++)
                #pragma unroll
                for (int j = 0; j < 4; j++) {
                    accG[i][j] = fmaf(av[i], bv[j], accG[i][j]);
                    accC[i][j] = fmaf(qv[i], kv[j], accC[i][j]);
                }
        }
    }
    #pragma unroll
    for (int i = 0; i < 4; i++) {
        size_t base = (size_t)(b*SS + s0 + ty*4 + i)*SS + t0 + tx*4;
        *(float4*)&g_G[base] = make_float4(accG[i][0], accG[i][1], accG[i][2], accG[i][3]);
        *(float4*)&g_W[base] = make_float4(accC[i][0], accC[i][1], accC[i][2], accC[i][3]);
    }
}

// ---------------- kernel 3: per-row quantiles (exact radix select) + softmax stats ----------------
__global__ void k_rowstats() {
    __shared__ float sdist[SS];     // 8 KB
    __shared__ float sscore[SS];    // 8 KB
    __shared__ unsigned s_hist[256];
    __shared__ int s_sel[2];
    __shared__ float red[256];
    int row = blockIdx.x;
    int tid = threadIdx.x;
    int colbase = (row >> 11) << 11;   // b*S
    const float* Grow = g_G + (size_t)row * SS;
    const float* Crow = g_W + (size_t)row * SS;
    float sqs = g_sq[row];
    float mx = -3.4e38f;
    for (int t = tid; t < SS; t += 256) {
        float g = Grow[t];
        float d2 = fmaxf(sqs + g_sq[colbase + t] - 2.0f*g, 0.0f);
        sdist[t] = d2 > 0.0f ? sqrtf(d2) : 0.0f;
        float sc = Crow[t] * 0.125f;   // / sqrt(64)
        sscore[t] = sc;
        mx = fmaxf(mx, sc);
    }
    red[tid] = mx;
    __syncthreads();
    for (int o = 128; o >= 1; o >>= 1) {
        if (tid < o) red[tid] = fmaxf(red[tid], red[tid + o]);
        __syncthreads();
    }
    mx = red[0];
    __syncthreads();
    float sm = 0.0f;
    for (int t = tid; t < SS; t += 256) sm += expf(sscore[t] - mx);
    red[tid] = sm;
    __syncthreads();
    for (int o = 128; o >= 1; o >>= 1) {
        if (tid < o) red[tid] += red[tid + o];
        __syncthreads();
    }
    float denom = red[0];

    // exact k-th smallest via MSB-first radix select (dist >= 0 -> uint order == float order)
    const unsigned* uv = (const unsigned*)sdist;
    float qv[4];
    const int ranks[4] = {102, 103, 1944, 1945};
    for (int r = 0; r < 4; r++) {
        unsigned prefix = 0;
        int kk = ranks[r];
        for (int shift = 24; shift >= 0; shift -= 8) {
            s_hist[tid] = 0u;
            __syncthreads();
            unsigned hm = (shift == 24) ? 0u : (0xffffffffu << (shift + 8));
            for (int t = tid; t < SS; t += 256) {
                unsigned v = uv[t];
                if ((v & hm) == prefix) atomicAdd(&s_hist[(v >> shift) & 255u], 1u);
            }
            __syncthreads();
            if (tid == 0) {
                int c = 0, d = 0;
                for (; d < 256; d++) {
                    int h = (int)s_hist[d];
                    if (c + h > kk) break;
                    c += h;
                }
                if (d > 255) d = 255;
                s_sel[0] = d; s_sel[1] = c;
            }
            __syncthreads();
            prefix |= ((unsigned)s_sel[0]) << shift;
            kk -= s_sel[1];
            __syncthreads();
        }
        qv[r] = __uint_as_float(prefix);
    }
    if (tid == 0) {
        float p05 = 0.05f * 2047.0f; int l05 = (int)p05; float f05 = p05 - (float)l05;
        float p95 = 0.95f * 2047.0f; int l95 = (int)p95; float f95 = p95 - (float)l95;
        (void)l05; (void)l95;
        float vmin = qv[0] + f05 * (qv[1] - qv[0]);
        float vmax = qv[2] + f95 * (qv[3] - qv[2]);
        g_stats[row] = make_float4(vmin, vmax, mx, denom);
    }
}

// ---------------- kernel 4a: W = exp(score - max - c*hybrid), in place over SC ----------------
__global__ void k_w(const float* __restrict__ alpha_p, const float* __restrict__ sigw_p) {
    size_t base = ((size_t)blockIdx.x * 256 + threadIdx.x) * 4;
    int row = (int)(base >> 11);
    int t0 = (int)(base & 2047);
    int colbase = (row >> 11) << 11;
    float4 g4 = *(const float4*)&g_G[base];
    float4 c4 = *(const float4*)&g_W[base];
    float4 st = g_stats[row];
    float sqs = g_sq[row], ins = g_invn[row];
    float a = 1.0f / (1.0f + expf(-alpha_p[0]));
    float sg = log1pf(expf(sigw_p[0])) + 0.001f;
    float cf = 1.0f / (2.0f * sg * sg);
    float rrange = 1.0f / (st.y - st.x + 1e-6f);
    float gg[4] = {g4.x, g4.y, g4.z, g4.w};
    float cc[4] = {c4.x, c4.y, c4.z, c4.w};
    float out[4];
    #pragma unroll
    for (int j = 0; j < 4; j++) {
        int t = t0 + j;
        float sqt = g_sq[colbase + t];
        float invt = g_invn[colbase + t];
        float g = gg[j];
        float d2 = fmaxf(sqs + sqt - 2.0f*g, 0.0f);
        float dist = d2 > 0.0f ? sqrtf(d2) : 0.0f;
        float cs = (g * ins * invt + 1.0f) * 0.5f;
        float eu = fminf(fmaxf((dist - st.x) * rrange, 0.0f), 1.0f);
        float hyb = a*cs + (1.0f - a)*(1.0f - eu);
        out[j] = expf(cc[j]*0.125f - st.z - cf*hyb);
    }
    *(float4*)&g_W[base] = make_float4(out[0], out[1], out[2], out[3]);
}

// ---------------- kernel 4b: pe = (W @ x) / denom, tiled ----------------
__global__ void k_pe(const float* __restrict__ x) {
    __shared__ float Wt[64][33];
    __shared__ float Xt[32][68];
    int tid = threadIdx.x;
    int b = blockIdx.y;
    int s0 = blockIdx.x * 64;
    int brow = b * SS;
    int tx = tid & 15, ty = tid >> 4;
    float acc[4][4] = {{0}};
    for (int tc = 0; tc < SS; tc += 32) {
        __syncthreads();
        for (int l = tid; l < 2048; l += 256) {
            int i = l >> 5, j = l & 31;
            Wt[i][j] = g_W[(size_t)(brow + s0 + i)*SS + tc + j];
        }
        for (int l = tid; l < 2048; l += 256) {
            int j = l >> 6, f = l & 63;
            Xt[j][f] = x[(size_t)(brow + tc + j)*FF + f];
        }
        __syncthreads();
        #pragma unroll 8
        for (int jt = 0; jt < 32; jt++) {
            float4 xv = *(const float4*)&Xt[jt][tx*4];
            float w0 = Wt[ty*4+0][jt];
            float w1 = Wt[ty*4+1][jt];
            float w2 = Wt[ty*4+2][jt];
            float w3 = Wt[ty*4+3][jt];
            acc[0][0] = fmaf(w0, xv.x, acc[0][0]); acc[0][1] = fmaf(w0, xv.y, acc[0][1]);
            acc[0][2] = fmaf(w0, xv.z, acc[0][2]); acc[0][3] = fmaf(w0, xv.w, acc[0][3]);
            acc[1][0] = fmaf(w1, xv.x, acc[1][0]); acc[1][1] = fmaf(w1, xv.y, acc[1][1]);
            acc[1][2] = fmaf(w1, xv.z, acc[1][2]); acc[1][3] = fmaf(w1, xv.w, acc[1][3]);
            acc[2][0] = fmaf(w2, xv.x, acc[2][0]); acc[2][1] = fmaf(w2, xv.y, acc[2][1]);
            acc[2][2] = fmaf(w2, xv.z, acc[2][2]); acc[2][3] = fmaf(w2, xv.w, acc[2][3]);
            acc[3][0] = fmaf(w3, xv.x, acc[3][0]); acc[3][1] = fmaf(w3, xv.y, acc[3][1]);
            acc[3][2] = fmaf(w3, xv.z, acc[3][2]); acc[3][3] = fmaf(w3, xv.w, acc[3][3]);
        }
    }
    #pragma unroll
    for (int i = 0; i < 4; i++) {
        int srow = brow + s0 + ty*4 + i;
        float dinv = 1.0f / g_stats[srow].w;
        *(float4*)&g_pe[(size_t)srow*FF + tx*4] =
            make_float4(acc[i][0]*dinv, acc[i][1]*dinv, acc[i][2]*dinv, acc[i][3]*dinv);
    }
}

// ---------------- kernel 5: projection + RPE branch + two layernorms ----------------
__global__ void k_final(const float* __restrict__ x,
                        const float* __restrict__ rpeW, const float* __restrict__ rpeb,
                        const float* __restrict__ projW, const float* __restrict__ projb,
                        const float* __restrict__ ln1w, const float* __restrict__ ln1b,
                        const float* __restrict__ ln2w, const float* __restrict__ ln2b,
                        const float* __restrict__ lns_p, const float* __restrict__ swgt,
                        float* __restrict__ out) {
    int row = blockIdx.x;
    int s = row & 2047;
    int tid = threadIdx.x;
    __shared__ float pe_s[FF];
    __shared__ float2 red[256];
    __shared__ float bc[4];
    if (tid < FF) pe_s[tid] = g_pe[(size_t)row*FF + tid];
    if (tid < 32) {
        float nmf = rintf(fminf(fmaxf(lns_p[0], 1.0f), 15.0f));
        int nmi = (int)nmf;
        float sdd = 0.0f, sde = 0.0f, swd = 0.0f;
        int sc = tid + 1;
        if (tid < 15 && sc <= nmi && s >= sc) {
            const float* xr = x + (size_t)row * FF;
            const float* xp = x + (size_t)(row - sc) * FF;
            float d0 = xp[0]     - xr[0];
            float e0 = xp[FF-1]  - xr[FF-1];
            sdd = d0; sde = e0;
            swd = swgt[sc-1] * expf(-fabsf(d0) * exp2f(-(float)sc));
        }
        #pragma unroll
        for (int o = 16; o >= 1; o >>= 1) {
            sdd += __shfl_xor_sync(0xffffffffu, sdd, o);
            sde += __shfl_xor_sync(0xffffffffu, sde, o);
            swd += __shfl_xor_sync(0xffffffffu, swd, o);
        }
        if (tid == 0) { bc[0] = sdd; bc[1] = sde; bc[2] = swd; bc[3] = nmf; }
    }
    __syncthreads();

    // pe @ proj_W + proj_b
    float y = projb[tid];
    #pragma unroll
    for (int f = 0; f < FF; f++) y = fmaf(pe_s[f], projW[f*DD + tid], y);

    // LN2(y)
    red[tid] = make_float2(y, y*y);
    __syncthreads();
    for (int o = 128; o >= 1; o >>= 1) {
        if (tid < o) { red[tid].x += red[tid+o].x; red[tid].y += red[tid+o].y; }
        __syncthreads();
    }
    float m = red[0].x * (1.0f/DD);
    float var = fmaxf(red[0].y * (1.0f/DD) - m*m, 0.0f);
    float lny = (y - m) * rsqrtf(var + 1e-5f) * ln2w[tid] + ln2b[tid];
    __syncthreads();

    // enc_sum and LN1
    float e = bc[3]*rpeb[tid] + bc[0]*rpeW[tid] + bc[1]*rpeW[DD + tid] + bc[2]*rpeW[2*DD + tid];
    red[tid] = make_float2(e, e*e);
    __syncthreads();
    for (int o = 128; o >= 1; o >>= 1) {
        if (tid < o) { red[tid].x += red[tid+o].x; red[tid].y += red[tid+o].y; }
        __syncthreads();
    }
    float m2 = red[0].x * (1.0f/DD);
    float var2 = fmaxf(red[0].y * (1.0f/DD) - m2*m2, 0.0f);
    float lne = (e - m2) * rsqrtf(var2 + 1e-5f) * ln1w[tid] + ln1b[tid];

    out[(size_t)row*DD + tid] = lne + lny;
}

// ---------------- launcher ----------------
extern "C" void kernel_launch(void* const* d_in, const int* in_sizes, int n_in,
                              void* d_out, int out_size) {
    const float* x     = (const float*)d_in[0];
    const float* rpeW  = (const float*)d_in[1];
    const float* rpeb  = (const float*)d_in[2];
    const float* projW = (const float*)d_in[3];
    const float* projb = (const float*)d_in[4];
    const float* ln1w  = (const float*)d_in[5];
    const float* ln1b  = (const float*)d_in[6];
    const float* ln2w  = (const float*)d_in[7];
    const float* ln2b  = (const float*)d_in[8];
    const float* alpha = (const float*)d_in[9];
    const float* sigw  = (const float*)d_in[10];
    const float* lns   = (const float*)d_in[11];
    const float* swgt  = (const float*)d_in[12];
    const float* qW    = (const float*)d_in[13];
    const float* qb    = (const float*)d_in[14];
    const float* kW    = (const float*)d_in[15];
    const float* kb    = (const float*)d_in[16];
    float* out = (float*)d_out;

    k_pre     <<<NROW/4, 256>>>(x, qW, qb, kW, kb);
    k_gemm1   <<<dim3(SS/64, SS/64, BB), 256>>>(x);
    k_rowstats<<<NROW, 256>>>();
    k_w       <<<(NROW*(SS/4))/256, 256>>>(alpha, sigw);
    k_pe      <<<dim3(SS/64, BB), 256>>>(x);
    k_final   <<<NROW, 256>>>(x, rpeW, rpeb, projW, projb,
                              ln1w, ln1b, ln2w, ln2b, lns, swgt, out);
}

// round 2
// speedup vs baseline: 1.5524x; 1.5524x over previous
#include <cuda_runtime.h>
#include <math.h>

#define BB 4
#define SS 2048
#define FF 64
#define DD 256
#define NROW (BB*SS)   // 8192

// ---------------- scratch (static __device__, no allocations) ----------------
__device__ float g_G[NROW*SS];      // 64 MB: x.x^T
__device__ float g_W[NROW*SS];      // 64 MB: q.k^T (raw scores, NOT overwritten)
__device__ float g_q[NROW*FF];
__device__ float g_k[NROW*FF];
__device__ float g_sq[NROW];
__device__ float g_invn[NROW];
__device__ float4 g_stats[NROW];    // vmin, vmax, rowmax(score), softmax denom
__device__ float g_pe[NROW*FF];

// ---------------- kernel 1: q/k projection + per-row norms ----------------
__global__ void k_pre(const float* __restrict__ x,
                      const float* __restrict__ qW, const float* __restrict__ qb,
                      const float* __restrict__ kW, const float* __restrict__ kb) {
    __shared__ float xs[4][FF];
    __shared__ float red[256];
    int tid = threadIdx.x;
    int ty = tid >> 6, f = tid & 63;
    int row = blockIdx.x * 4 + ty;
    float xv = x[(size_t)row*FF + f];
    xs[ty][f] = xv;
    red[tid] = xv * xv;
    __syncthreads();
    #pragma unroll
    for (int o = 32; o >= 1; o >>= 1) {
        if (f < o) red[tid] += red[tid + o];
        __syncthreads();
    }
    float q = qb[f], k = kb[f];
    #pragma unroll
    for (int g = 0; g < FF; g++) {
        float xg = xs[ty][g];
        q = fmaf(xg, qW[g*FF + f], q);
        k = fmaf(xg, kW[g*FF + f], k);
    }
    g_q[(size_t)row*FF + f] = q;
    g_k[(size_t)row*FF + f] = k;
    if (f == 0) {
        float sq = red[ty*64];
        g_sq[row] = sq;
        g_invn[row] = 1.0f / fmaxf(sqrtf(sq), 1e-12f);
    }
}

// ---------------- kernel 2: G = x.x^T and SC = q.k^T, 64x64 tiles ----------------
__global__ void k_gemm1(const float* __restrict__ x) {
    __shared__ float Xs[32][68], Xt[32][68], Qs[32][68], Kt[32][68];
    int tid = threadIdx.x;
    int b = blockIdx.z;
    int s0 = blockIdx.y * 64, t0 = blockIdx.x * 64;
    const float* xb = x   + (size_t)b*SS*FF;
    const float* qb_ = g_q + (size_t)b*SS*FF;
    const float* kb_ = g_k + (size_t)b*SS*FF;
    int tx = tid & 15, ty = tid >> 4;
    float accG[4][4] = {{0}}, accC[4][4] = {{0}};
    for (int fc = 0; fc < FF; fc += 32) {
        __syncthreads();
        for (int l = tid; l < 64*32; l += 256) {
            int i = l >> 5, f = l & 31;
            Xs[f][i] = xb[(size_t)(s0+i)*FF + fc + f];
            Qs[f][i] = qb_[(size_t)(s0+i)*FF + fc + f];
            Xt[f][i] = xb[(size_t)(t0+i)*FF + fc + f];
            Kt[f][i] = kb_[(size_t)(t0+i)*FF + fc + f];
        }
        __syncthreads();
        #pragma unroll 8
        for (int f = 0; f < 32; f++) {
            float4 ax = *(const float4*)&Xs[f][ty*4];
            float4 aq = *(const float4*)&Qs[f][ty*4];
            float4 bx = *(const float4*)&Xt[f][tx*4];
            float4 bk = *(const float4*)&Kt[f][tx*4];
            float av[4] = {ax.x, ax.y, ax.z, ax.w};
            float qv[4] = {aq.x, aq.y, aq.z, aq.w};
            float bv[4] = {bx.x, bx.y, bx.z, bx.w};
            float kv[4] = {bk.x, bk.y, bk.z, bk.w};
            #pragma unroll
            for (int i = 0; i < 4; i++)
                #pragma unroll
                for (int j = 0; j < 4; j++) {
                    accG[i][j] = fmaf(av[i], bv[j], accG[i][j]);
                    accC[i][j] = fmaf(qv[i], kv[j], accC[i][j]);
                }
        }
    }
    #pragma unroll
    for (int i = 0; i < 4; i++) {
        size_t base = (size_t)(b*SS + s0 + ty*4 + i)*SS + t0 + tx*4;
        *(float4*)&g_G[base] = make_float4(accG[i][0], accG[i][1], accG[i][2], accG[i][3]);
        *(float4*)&g_W[base] = make_float4(accC[i][0], accC[i][1], accC[i][2], accC[i][3]);
    }
}

// ---------------- kernel 3: per-row quantiles + softmax stats (parallel select) ----------------
__global__ void k_rowstats() {
    __shared__ float sdist[SS];        // 8 KB
    __shared__ float2 red2[256];       // online-softmax reduction
    __shared__ unsigned s_hist[256];
    __shared__ unsigned s_warp[8];
    __shared__ unsigned s_sel[2];
    __shared__ uint4 red4[256];        // neighbor scan reduction
    int row = blockIdx.x;
    int tid = threadIdx.x;
    int lane = tid & 31, wid = tid >> 5;
    int colbase = (row >> 11) << 11;   // b*S
    const float* Grow = g_G + (size_t)row * SS;
    const float* Crow = g_W + (size_t)row * SS;
    float sqs = g_sq[row];

    // pass 1: build dist row in shared; online softmax of scores
    float m = -3.4e38f, sm = 0.0f;
    #pragma unroll
    for (int u = 0; u < 8; u++) {
        int t = tid + u*256;
        float g = Grow[t];
        float d2 = fmaxf(sqs + g_sq[colbase + t] - 2.0f*g, 0.0f);
        sdist[t] = d2 > 0.0f ? sqrtf(d2) : 0.0f;
        float sc = Crow[t] * 0.125f;
        float nm = fmaxf(m, sc);
        sm = sm * __expf(m - nm) + __expf(sc - nm);
        m = nm;
    }
    red2[tid] = make_float2(m, sm);
    __syncthreads();
    #pragma unroll
    for (int o = 128; o >= 1; o >>= 1) {
        if (tid < o) {
            float2 a = red2[tid], bq = red2[tid + o];
            float M = fmaxf(a.x, bq.x);
            red2[tid] = make_float2(M, a.y*__expf(a.x - M) + bq.y*__expf(bq.x - M));
        }
        __syncthreads();
    }
    float mx = red2[0].x, denom = red2[0].y;
    __syncthreads();

    // exact radix selects for 0-indexed ranks 102 and 1944
    const unsigned* uv = (const unsigned*)sdist;
    unsigned qa = 0, qb2 = 0;
    const int base_ranks[2] = {102, 1944};
    #pragma unroll
    for (int r = 0; r < 2; r++) {
        unsigned prefix = 0;
        int kk = base_ranks[r];
        #pragma unroll
        for (int shift = 24; shift >= 0; shift -= 8) {
            s_hist[tid] = 0u;
            __syncthreads();
            unsigned hm = (shift == 24) ? 0u : (0xffffffffu << (shift + 8));
            #pragma unroll
            for (int u = 0; u < 8; u++) {
                unsigned v = uv[tid + u*256];
                if ((v & hm) == prefix) atomicAdd(&s_hist[(v >> shift) & 255u], 1u);
            }
            __syncthreads();
            unsigned h = s_hist[tid];
            unsigned incl = h;
            #pragma unroll
            for (int o = 1; o < 32; o <<= 1) {
                unsigned n = __shfl_up_sync(0xffffffffu, incl, o);
                if (lane >= o) incl += n;
            }
            if (lane == 31) s_warp[wid] = incl;
            __syncthreads();
            if (tid < 8) {
                unsigned w = s_warp[tid];
                #pragma unroll
                for (int o = 1; o < 8; o <<= 1) {
                    unsigned n = __shfl_up_sync(0xffu, w, o, 8);
                    if (tid >= o) w += n;
                }
                s_warp[tid] = w;
            }
            __syncthreads();
            unsigned wbase = (wid > 0) ? s_warp[wid - 1] : 0u;
            unsigned excl = wbase + incl - h;
            if ((unsigned)kk >= excl && (unsigned)kk < excl + h) {
                s_sel[0] = (unsigned)tid; s_sel[1] = excl;
            }
            __syncthreads();
            prefix |= s_sel[0] << shift;
            kk -= (int)s_sel[1];
            __syncthreads();
        }
        if (r == 0) qa = prefix; else qb2 = prefix;
    }

    // neighbor ranks (103, 1945): count<=v and min of values>v, one scan
    unsigned ca = 0, cb = 0, ma = 0xffffffffu, mb = 0xffffffffu;
    #pragma unroll
    for (int u = 0; u < 8; u++) {
        unsigned v = uv[tid + u*256];
        if (v <= qa) ca++; else ma = min(ma, v);
        if (v <= qb2) cb++; else mb = min(mb, v);
    }
    red4[tid] = make_uint4(ca, ma, cb, mb);
    __syncthreads();
    #pragma unroll
    for (int o = 128; o >= 1; o >>= 1) {
        if (tid < o) {
            uint4 a = red4[tid], bq = red4[tid + o];
            red4[tid] = make_uint4(a.x + bq.x, min(a.y, bq.y), a.z + bq.z, min(a.w, bq.w));
        }
        __syncthreads();
    }
    if (tid == 0) {
        uint4 rr = red4[0];
        float v102 = __uint_as_float(qa);
        float v103 = (rr.x >= 104u)  ? v102 : __uint_as_float(rr.y);
        float v1944 = __uint_as_float(qb2);
        float v1945 = (rr.z >= 1946u) ? v1944 : __uint_as_float(rr.w);
        float f05 = 0.05f * 2047.0f - 102.0f;
        float f95 = 0.95f * 2047.0f - 1944.0f;
        float vmin = v102 + f05 * (v103 - v102);
        float vmax = v1944 + f95 * (v1945 - v1944);
        g_stats[row] = make_float4(vmin, vmax, mx, denom);
    }
}

// ---------------- kernel 4: pe = (W @ x) / denom with W computed on the fly ----------------
__global__ void k_pe_fused(const float* __restrict__ x,
                           const float* __restrict__ alpha_p,
                           const float* __restrict__ sigw_p) {
    __shared__ float Wt[64][33];
    __shared__ float Xt[32][68];
    __shared__ float4 sstats[64];
    __shared__ float ssq[64], sinv[64], srr[64], sdiv[64];
    __shared__ float csq[32], cinv[32];
    int tid = threadIdx.x;
    int b = blockIdx.y;
    int s0 = blockIdx.x * 64;
    int brow = b * SS;
    int tx = tid & 15, ty = tid >> 4;

    if (tid < 64) {
        int gr = brow + s0 + tid;
        float4 st = g_stats[gr];
        sstats[tid] = st;
        ssq[tid] = g_sq[gr];
        sinv[tid] = g_invn[gr];
        srr[tid] = 1.0f / (st.y - st.x + 1e-6f);
        sdiv[tid] = 1.0f / st.w;
    }
    float a = 1.0f / (1.0f + __expf(-alpha_p[0]));
    float sg = log1pf(expf(sigw_p[0])) + 0.001f;
    float cf = 1.0f / (2.0f * sg * sg);
    float one_m_a = 1.0f - a;

    float acc[4][4] = {{0}};
    for (int tc = 0; tc < SS; tc += 32) {
        __syncthreads();   // prev Wt/Xt consumed, stats visible (first iter)
        // stage G/C loads into registers
        float gvr[8], cvr[8];
        #pragma unroll
        for (int u = 0; u < 8; u++) {
            int l = tid + u*256;
            int i = l >> 5, j = l & 31;
            size_t off = (size_t)(brow + s0 + i)*SS + tc + j;
            gvr[u] = g_G[off];
            cvr[u] = g_W[off];
        }
        if (tid < 32) {
            csq[tid]  = g_sq[brow + tc + tid];
            cinv[tid] = g_invn[brow + tc + tid];
        }
        // load X tile
        #pragma unroll
        for (int u = 0; u < 8; u++) {
            int l = tid + u*256;
            int j = l >> 6, f = l & 63;
            Xt[j][f] = x[(size_t)(brow + tc + j)*FF + f];
        }
        __syncthreads();   // csq visible
        // compute W tile
        #pragma unroll
        for (int u = 0; u < 8; u++) {
            int l = tid + u*256;
            int i = l >> 5, j = l & 31;
            float4 st = sstats[i];
            float g = gvr[u];
            float d2 = fmaxf(ssq[i] + csq[j] - 2.0f*g, 0.0f);
            float dist = d2 > 0.0f ? sqrtf(d2) : 0.0f;
            float cs = fmaf(g * sinv[i], cinv[j], 1.0f) * 0.5f;
            float eu = fminf(fmaxf((dist - st.x) * srr[i], 0.0f), 1.0f);
            float hyb = fmaf(a, cs, one_m_a * (1.0f - eu));
            Wt[i][j] = __expf(fmaf(cvr[u], 0.125f, -st.z) - cf*hyb);
        }
        __syncthreads();   // Wt visible
        #pragma unroll 8
        for (int jt = 0; jt < 32; jt++) {
            float4 xv = *(const float4*)&Xt[jt][tx*4];
            float w0 = Wt[ty*4+0][jt];
            float w1 = Wt[ty*4+1][jt];
            float w2 = Wt[ty*4+2][jt];
            float w3 = Wt[ty*4+3][jt];
            acc[0][0] = fmaf(w0, xv.x, acc[0][0]); acc[0][1] = fmaf(w0, xv.y, acc[0][1]);
            acc[0][2] = fmaf(w0, xv.z, acc[0][2]); acc[0][3] = fmaf(w0, xv.w, acc[0][3]);
            acc[1][0] = fmaf(w1, xv.x, acc[1][0]); acc[1][1] = fmaf(w1, xv.y, acc[1][1]);
            acc[1][2] = fmaf(w1, xv.z, acc[1][2]); acc[1][3] = fmaf(w1, xv.w, acc[1][3]);
            acc[2][0] = fmaf(w2, xv.x, acc[2][0]); acc[2][1] = fmaf(w2, xv.y, acc[2][1]);
            acc[2][2] = fmaf(w2, xv.z, acc[2][2]); acc[2][3] = fmaf(w2, xv.w, acc[2][3]);
            acc[3][0] = fmaf(w3, xv.x, acc[3][0]); acc[3][1] = fmaf(w3, xv.y, acc[3][1]);
            acc[3][2] = fmaf(w3, xv.z, acc[3][2]); acc[3][3] = fmaf(w3, xv.w, acc[3][3]);
        }
    }
    #pragma unroll
    for (int i = 0; i < 4; i++) {
        int li = ty*4 + i;
        int srow = brow + s0 + li;
        float dinv = sdiv[li];
        *(float4*)&g_pe[(size_t)srow*FF + tx*4] =
            make_float4(acc[i][0]*dinv, acc[i][1]*dinv, acc[i][2]*dinv, acc[i][3]*dinv);
    }
}

// ---------------- kernel 5: projection + RPE branch + two layernorms ----------------
__global__ void k_final(const float* __restrict__ x,
                        const float* __restrict__ rpeW, const float* __restrict__ rpeb,
                        const float* __restrict__ projW, const float* __restrict__ projb,
                        const float* __restrict__ ln1w, const float* __restrict__ ln1b,
                        const float* __restrict__ ln2w, const float* __restrict__ ln2b,
                        const float* __restrict__ lns_p, const float* __restrict__ swgt,
                        float* __restrict__ out) {
    int row = blockIdx.x;
    int s = row & 2047;
    int tid = threadIdx.x;
    __shared__ float pe_s[FF];
    __shared__ float2 red[256];
    __shared__ float bc[4];
    if (tid < FF) pe_s[tid] = g_pe[(size_t)row*FF + tid];
    if (tid < 32) {
        float nmf = rintf(fminf(fmaxf(lns_p[0], 1.0f), 15.0f));
        int nmi = (int)nmf;
        float sdd = 0.0f, sde = 0.0f, swd = 0.0f;
        int sc = tid + 1;
        if (tid < 15 && sc <= nmi && s >= sc) {
            const float* xr = x + (size_t)row * FF;
            const float* xp = x + (size_t)(row - sc) * FF;
            float d0 = xp[0]     - xr[0];
            float e0 = xp[FF-1]  - xr[FF-1];
            sdd = d0; sde = e0;
            swd = swgt[sc-1] * expf(-fabsf(d0) * exp2f(-(float)sc));
        }
        #pragma unroll
        for (int o = 16; o >= 1; o >>= 1) {
            sdd += __shfl_xor_sync(0xffffffffu, sdd, o);
            sde += __shfl_xor_sync(0xffffffffu, sde, o);
            swd += __shfl_xor_sync(0xffffffffu, swd, o);
        }
        if (tid == 0) { bc[0] = sdd; bc[1] = sde; bc[2] = swd; bc[3] = nmf; }
    }
    __syncthreads();

    // pe @ proj_W + proj_b
    float y = projb[tid];
    #pragma unroll
    for (int f = 0; f < FF; f++) y = fmaf(pe_s[f], projW[f*DD + tid], y);

    // LN2(y)
    red[tid] = make_float2(y, y*y);
    __syncthreads();
    for (int o = 128; o >= 1; o >>= 1) {
        if (tid < o) { red[tid].x += red[tid+o].x; red[tid].y += red[tid+o].y; }
        __syncthreads();
    }
    float m = red[0].x * (1.0f/DD);
    float var = fmaxf(red[0].y * (1.0f/DD) - m*m, 0.0f);
    float lny = (y - m) * rsqrtf(var + 1e-5f) * ln2w[tid] + ln2b[tid];
    __syncthreads();

    // enc_sum and LN1
    float e = bc[3]*rpeb[tid] + bc[0]*rpeW[tid] + bc[1]*rpeW[DD + tid] + bc[2]*rpeW[2*DD + tid];
    red[tid] = make_float2(e, e*e);
    __syncthreads();
    for (int o = 128; o >= 1; o >>= 1) {
        if (tid < o) { red[tid].x += red[tid+o].x; red[tid].y += red[tid+o].y; }
        __syncthreads();
    }
    float m2 = red[0].x * (1.0f/DD);
    float var2 = fmaxf(red[0].y * (1.0f/DD) - m2*m2, 0.0f);
    float lne = (e - m2) * rsqrtf(var2 + 1e-5f) * ln1w[tid] + ln1b[tid];

    out[(size_t)row*DD + tid] = lne + lny;
}

// ---------------- launcher ----------------
extern "C" void kernel_launch(void* const* d_in, const int* in_sizes, int n_in,
                              void* d_out, int out_size) {
    const float* x     = (const float*)d_in[0];
    const float* rpeW  = (const float*)d_in[1];
    const float* rpeb  = (const float*)d_in[2];
    const float* projW = (const float*)d_in[3];
    const float* projb = (const float*)d_in[4];
    const float* ln1w  = (const float*)d_in[5];
    const float* ln1b  = (const float*)d_in[6];
    const float* ln2w  = (const float*)d_in[7];
    const float* ln2b  = (const float*)d_in[8];
    const float* alpha = (const float*)d_in[9];
    const float* sigw  = (const float*)d_in[10];
    const float* lns   = (const float*)d_in[11];
    const float* swgt  = (const float*)d_in[12];
    const float* qW    = (const float*)d_in[13];
    const float* qb    = (const float*)d_in[14];
    const float* kW    = (const float*)d_in[15];
    const float* kb    = (const float*)d_in[16];
    float* out = (float*)d_out;

    k_pre     <<<NROW/4, 256>>>(x, qW, qb, kW, kb);
    k_gemm1   <<<dim3(SS/64, SS/64, BB), 256>>>(x);
    k_rowstats<<<NROW, 256>>>();
    k_pe_fused<<<dim3(SS/64, BB), 256>>>(x, alpha, sigw);
    k_final   <<<NROW, 256>>>(x, rpeW, rpeb, projW, projb,
                              ln1w, ln1b, ln2w, ln2b, lns, swgt, out);
}

// round 4
// speedup vs baseline: 1.8556x; 1.1953x over previous
#include <cuda_runtime.h>
#include <math.h>

#define BB 4
#define SS 2048
#define FF 64
#define DD 256
#define NROW (BB*SS)   // 8192
#define NSPLIT 4
#define TCHUNK (SS/NSPLIT)   // 512

// ---------------- scratch (static __device__, no allocations) ----------------
__device__ float g_G[NROW*SS];      // 64 MB: x.x^T
__device__ float g_W[NROW*SS];      // 64 MB: q.k^T (raw scores)
__device__ float g_q[NROW*FF];
__device__ float g_k[NROW*FF];
__device__ float g_sq[NROW];
__device__ float g_invn[NROW];
__device__ float4 g_stats[NROW];    // vmin, vmax, rowmax(score), softmax denom
__device__ float g_peP[NSPLIT*NROW*FF];   // 8 MB partial sums

// ---------------- kernel 1: q/k projection + per-row norms ----------------
__global__ void k_pre(const float* __restrict__ x,
                      const float* __restrict__ qW, const float* __restrict__ qb,
                      const float* __restrict__ kW, const float* __restrict__ kb) {
    __shared__ float xs[4][FF];
    __shared__ float red[256];
    int tid = threadIdx.x;
    int ty = tid >> 6, f = tid & 63;
    int row = blockIdx.x * 4 + ty;
    float xv = x[(size_t)row*FF + f];
    xs[ty][f] = xv;
    red[tid] = xv * xv;
    __syncthreads();
    #pragma unroll
    for (int o = 32; o >= 1; o >>= 1) {
        if (f < o) red[tid] += red[tid + o];
        __syncthreads();
    }
    float q = qb[f], k = kb[f];
    #pragma unroll
    for (int g = 0; g < FF; g++) {
        float xg = xs[ty][g];
        q = fmaf(xg, qW[g*FF + f], q);
        k = fmaf(xg, kW[g*FF + f], k);
    }
    g_q[(size_t)row*FF + f] = q;
    g_k[(size_t)row*FF + f] = k;
    if (f == 0) {
        float sq = red[ty*64];
        g_sq[row] = sq;
        g_invn[row] = 1.0f / fmaxf(sqrtf(sq), 1e-12f);
    }
}

// ---------------- kernel 2: G = x.x^T and SC = q.k^T, 64x64 tiles ----------------
__global__ void k_gemm1(const float* __restrict__ x) {
    __shared__ float Xs[32][68], Xt[32][68], Qs[32][68], Kt[32][68];
    int tid = threadIdx.x;
    int b = blockIdx.z;
    int s0 = blockIdx.y * 64, t0 = blockIdx.x * 64;
    const float* xb = x   + (size_t)b*SS*FF;
    const float* qb_ = g_q + (size_t)b*SS*FF;
    const float* kb_ = g_k + (size_t)b*SS*FF;
    int tx = tid & 15, ty = tid >> 4;
    float accG[4][4] = {{0}}, accC[4][4] = {{0}};
    for (int fc = 0; fc < FF; fc += 32) {
        __syncthreads();
        for (int l = tid; l < 64*32; l += 256) {
            int i = l >> 5, f = l & 31;
            Xs[f][i] = xb[(size_t)(s0+i)*FF + fc + f];
            Qs[f][i] = qb_[(size_t)(s0+i)*FF + fc + f];
            Xt[f][i] = xb[(size_t)(t0+i)*FF + fc + f];
            Kt[f][i] = kb_[(size_t)(t0+i)*FF + fc + f];
        }
        __syncthreads();
        #pragma unroll 8
        for (int f = 0; f < 32; f++) {
            float4 ax = *(const float4*)&Xs[f][ty*4];
            float4 aq = *(const float4*)&Qs[f][ty*4];
            float4 bx = *(const float4*)&Xt[f][tx*4];
            float4 bk = *(const float4*)&Kt[f][tx*4];
            float av[4] = {ax.x, ax.y, ax.z, ax.w};
            float qv[4] = {aq.x, aq.y, aq.z, aq.w};
            float bv[4] = {bx.x, bx.y, bx.z, bx.w};
            float kv[4] = {bk.x, bk.y, bk.z, bk.w};
            #pragma unroll
            for (int i = 0; i < 4; i++)
                #pragma unroll
                for (int j = 0; j < 4; j++) {
                    accG[i][j] = fmaf(av[i], bv[j], accG[i][j]);
                    accC[i][j] = fmaf(qv[i], kv[j], accC[i][j]);
                }
        }
    }
    #pragma unroll
    for (int i = 0; i < 4; i++) {
        size_t base = (size_t)(b*SS + s0 + ty*4 + i)*SS + t0 + tx*4;
        *(float4*)&g_G[base] = make_float4(accG[i][0], accG[i][1], accG[i][2], accG[i][3]);
        *(float4*)&g_W[base] = make_float4(accC[i][0], accC[i][1], accC[i][2], accC[i][3]);
    }
}

// ---------------- kernel 3: per-row quantiles + softmax stats (parallel select) ----------------
__global__ void k_rowstats() {
    __shared__ float sdist[SS];        // 8 KB
    __shared__ float2 red2[256];
    __shared__ unsigned s_hist[256];
    __shared__ unsigned s_warp[8];
    __shared__ unsigned s_sel[2];
    __shared__ uint4 red4[256];
    int row = blockIdx.x;
    int tid = threadIdx.x;
    int lane = tid & 31, wid = tid >> 5;
    int colbase = (row >> 11) << 11;
    const float* Grow = g_G + (size_t)row * SS;
    const float* Crow = g_W + (size_t)row * SS;
    float sqs = g_sq[row];

    float m = -3.4e38f, sm = 0.0f;
    #pragma unroll
    for (int u = 0; u < 8; u++) {
        int t = tid + u*256;
        float g = Grow[t];
        float d2 = fmaxf(sqs + g_sq[colbase + t] - 2.0f*g, 0.0f);
        sdist[t] = d2 > 0.0f ? sqrtf(d2) : 0.0f;
        float sc = Crow[t] * 0.125f;
        float nm = fmaxf(m, sc);
        sm = sm * __expf(m - nm) + __expf(sc - nm);
        m = nm;
    }
    red2[tid] = make_float2(m, sm);
    __syncthreads();
    #pragma unroll
    for (int o = 128; o >= 1; o >>= 1) {
        if (tid < o) {
            float2 a = red2[tid], bq = red2[tid + o];
            float M = fmaxf(a.x, bq.x);
            red2[tid] = make_float2(M, a.y*__expf(a.x - M) + bq.y*__expf(bq.x - M));
        }
        __syncthreads();
    }
    float mx = red2[0].x, denom = red2[0].y;
    __syncthreads();

    const unsigned* uv = (const unsigned*)sdist;
    unsigned qa = 0, qb2 = 0;
    const int base_ranks[2] = {102, 1944};
    #pragma unroll
    for (int r = 0; r < 2; r++) {
        unsigned prefix = 0;
        int kk = base_ranks[r];
        #pragma unroll
        for (int shift = 24; shift >= 0; shift -= 8) {
            s_hist[tid] = 0u;
            __syncthreads();
            unsigned hm = (shift == 24) ? 0u : (0xffffffffu << (shift + 8));
            #pragma unroll
            for (int u = 0; u < 8; u++) {
                unsigned v = uv[tid + u*256];
                if ((v & hm) == prefix) atomicAdd(&s_hist[(v >> shift) & 255u], 1u);
            }
            __syncthreads();
            unsigned h = s_hist[tid];
            unsigned incl = h;
            #pragma unroll
            for (int o = 1; o < 32; o <<= 1) {
                unsigned n = __shfl_up_sync(0xffffffffu, incl, o);
                if (lane >= o) incl += n;
            }
            if (lane == 31) s_warp[wid] = incl;
            __syncthreads();
            if (tid < 8) {
                unsigned w = s_warp[tid];
                #pragma unroll
                for (int o = 1; o < 8; o <<= 1) {
                    unsigned n = __shfl_up_sync(0xffu, w, o, 8);
                    if (tid >= o) w += n;
                }
                s_warp[tid] = w;
            }
            __syncthreads();
            unsigned wbase = (wid > 0) ? s_warp[wid - 1] : 0u;
            unsigned excl = wbase + incl - h;
            if ((unsigned)kk >= excl && (unsigned)kk < excl + h) {
                s_sel[0] = (unsigned)tid; s_sel[1] = excl;
            }
            __syncthreads();
            prefix |= s_sel[0] << shift;
            kk -= (int)s_sel[1];
            __syncthreads();
        }
        if (r == 0) qa = prefix; else qb2 = prefix;
    }

    unsigned ca = 0, cb = 0, ma = 0xffffffffu, mb = 0xffffffffu;
    #pragma unroll
    for (int u = 0; u < 8; u++) {
        unsigned v = uv[tid + u*256];
        if (v <= qa) ca++; else ma = min(ma, v);
        if (v <= qb2) cb++; else mb = min(mb, v);
    }
    red4[tid] = make_uint4(ca, ma, cb, mb);
    __syncthreads();
    #pragma unroll
    for (int o = 128; o >= 1; o >>= 1) {
        if (tid < o) {
            uint4 a = red4[tid], bq = red4[tid + o];
            red4[tid] = make_uint4(a.x + bq.x, min(a.y, bq.y), a.z + bq.z, min(a.w, bq.w));
        }
        __syncthreads();
    }
    if (tid == 0) {
        uint4 rr = red4[0];
        float v102 = __uint_as_float(qa);
        float v103 = (rr.x >= 104u)  ? v102 : __uint_as_float(rr.y);
        float v1944 = __uint_as_float(qb2);
        float v1945 = (rr.z >= 1946u) ? v1944 : __uint_as_float(rr.w);
        float f05 = 0.05f * 2047.0f - 102.0f;
        float f95 = 0.95f * 2047.0f - 1944.0f;
        float vmin = v102 + f05 * (v103 - v102);
        float vmax = v1944 + f95 * (v1945 - v1944);
        g_stats[row] = make_float4(vmin, vmax, mx, denom);
    }
}

// ---------------- kernel 4: partial pe = W @ x over a 512-col chunk, W on the fly ----------------
__global__ void __launch_bounds__(256, 2)
k_pe_fused(const float* __restrict__ x,
           const float* __restrict__ alpha_p,
           const float* __restrict__ sigw_p) {
    __shared__ float Wt[64][33];
    __shared__ float Xt[32][68];
    __shared__ float sminv[64], smax[64];   // vmin, rowmax
    __shared__ float ssq[64], sinv[64], srr[64];
    __shared__ float csq[TCHUNK], cinv[TCHUNK];
    int tid = threadIdx.x;
    int b = blockIdx.z;
    int s0 = blockIdx.x * 64;
    int tc0 = blockIdx.y * TCHUNK;
    int brow = b * SS;
    int tx = tid & 15, ty = tid >> 4;

    if (tid < 64) {
        int gr = brow + s0 + tid;
        float4 st = g_stats[gr];
        sminv[tid] = st.x;
        smax[tid] = st.z;
        ssq[tid] = g_sq[gr];
        sinv[tid] = g_invn[gr];
        srr[tid] = 1.0f / (st.y - st.x + 1e-6f);
    }
    #pragma unroll
    for (int u = 0; u < TCHUNK/256; u++) {
        int t = tid + u*256;
        csq[t]  = g_sq[brow + tc0 + t];
        cinv[t] = g_invn[brow + tc0 + t];
    }
    float a = 1.0f / (1.0f + __expf(-alpha_p[0]));
    float sg = log1pf(expf(sigw_p[0])) + 0.001f;
    float cf = 1.0f / (2.0f * sg * sg);
    float one_m_a = 1.0f - a;
    __syncthreads();   // per-chunk tables visible

    float acc[4][4] = {{0}};
    for (int tc = tc0; tc < tc0 + TCHUNK; tc += 32) {
        // stage G/C tile into registers (float4, coalesced)
        float4 g4[2], c4[2];
        #pragma unroll
        for (int u = 0; u < 2; u++) {
            int l = tid + u*256;             // 0..511 float4 slots
            int i = l >> 3, j4 = l & 7;
            size_t off = (size_t)(brow + s0 + i)*SS + tc + j4*4;
            g4[u] = *(const float4*)&g_G[off];
            c4[u] = *(const float4*)&g_W[off];
        }
        // X tile
        #pragma unroll
        for (int u = 0; u < 2; u++) {
            int l = tid + u*256;
            int j = l >> 4, f4 = l & 15;
            *(float4*)&Xt[j][f4*4] = *(const float4*)&x[(size_t)(brow + tc + j)*FF + f4*4];
        }
        // compute W tile
        #pragma unroll
        for (int u = 0; u < 2; u++) {
            int l = tid + u*256;
            int i = l >> 3, j4 = l & 7;
            int jb = (tc - tc0) + j4*4;
            float gg[4] = {g4[u].x, g4[u].y, g4[u].z, g4[u].w};
            float cc[4] = {c4[u].x, c4[u].y, c4[u].z, c4[u].w};
            float vmin = sminv[i], rr = srr[i], mxs = smax[i];
            float sqi = ssq[i], ivi = sinv[i];
            #pragma unroll
            for (int e = 0; e < 4; e++) {
                float g = gg[e];
                float d2 = fmaxf(sqi + csq[jb+e] - 2.0f*g, 0.0f);
                float dist = d2 > 0.0f ? sqrtf(d2) : 0.0f;
                float cs = fmaf(g * ivi, cinv[jb+e], 1.0f) * 0.5f;
                float eu = fminf(fmaxf((dist - vmin) * rr, 0.0f), 1.0f);
                float hyb = fmaf(a, cs, one_m_a * (1.0f - eu));
                Wt[i][j4*4+e] = __expf(fmaf(cc[e], 0.125f, -mxs) - cf*hyb);
            }
        }
        __syncthreads();   // Wt/Xt visible
        #pragma unroll 8
        for (int jt = 0; jt < 32; jt++) {
            float4 xv = *(const float4*)&Xt[jt][tx*4];
            float w0 = Wt[ty*4+0][jt];
            float w1 = Wt[ty*4+1][jt];
            float w2 = Wt[ty*4+2][jt];
            float w3 = Wt[ty*4+3][jt];
            acc[0][0] = fmaf(w0, xv.x, acc[0][0]); acc[0][1] = fmaf(w0, xv.y, acc[0][1]);
            acc[0][2] = fmaf(w0, xv.z, acc[0][2]); acc[0][3] = fmaf(w0, xv.w, acc[0][3]);
            acc[1][0] = fmaf(w1, xv.x, acc[1][0]); acc[1][1] = fmaf(w1, xv.y, acc[1][1]);
            acc[1][2] = fmaf(w1, xv.z, acc[1][2]); acc[1][3] = fmaf(w1, xv.w, acc[1][3]);
            acc[2][0] = fmaf(w2, xv.x, acc[2][0]); acc[2][1] = fmaf(w2, xv.y, acc[2][1]);
            acc[2][2] = fmaf(w2, xv.z, acc[2][2]); acc[2][3] = fmaf(w2, xv.w, acc[2][3]);
            acc[3][0] = fmaf(w3, xv.x, acc[3][0]); acc[3][1] = fmaf(w3, xv.y, acc[3][1]);
            acc[3][2] = fmaf(w3, xv.z, acc[3][2]); acc[3][3] = fmaf(w3, xv.w, acc[3][3]);
        }
        __syncthreads();   // tile consumed
    }
    float* outp = g_peP + (size_t)blockIdx.y * NROW * FF;
    #pragma unroll
    for (int i = 0; i < 4; i++) {
        int srow = brow + s0 + ty*4 + i;
        *(float4*)&outp[(size_t)srow*FF + tx*4] =
            make_float4(acc[i][0], acc[i][1], acc[i][2], acc[i][3]);
    }
}

// ---------------- kernel 5: projection + RPE branch + two layernorms ----------------
__global__ void k_final(const float* __restrict__ x,
                        const float* __restrict__ rpeW, const float* __restrict__ rpeb,
                        const float* __restrict__ projW, const float* __restrict__ projb,
                        const float* __restrict__ ln1w, const float* __restrict__ ln1b,
                        const float* __restrict__ ln2w, const float* __restrict__ ln2b,
                        const float* __restrict__ lns_p, const float* __restrict__ swgt,
                        float* __restrict__ out) {
    int row = blockIdx.x;
    int s = row & 2047;
    int tid = threadIdx.x;
    __shared__ float pe_s[FF];
    __shared__ float2 red[256];
    __shared__ float bc[4];
    if (tid < FF) {
        float v = g_peP[(size_t)row*FF + tid]
                + g_peP[(size_t)NROW*FF   + (size_t)row*FF + tid]
                + g_peP[(size_t)NROW*FF*2 + (size_t)row*FF + tid]
                + g_peP[(size_t)NROW*FF*3 + (size_t)row*FF + tid];
        pe_s[tid] = v / g_stats[row].w;
    }
    if (tid < 32) {
        float nmf = rintf(fminf(fmaxf(lns_p[0], 1.0f), 15.0f));
        int nmi = (int)nmf;
        float sdd = 0.0f, sde = 0.0f, swd = 0.0f;
        int sc = tid + 1;
        if (tid < 15 && sc <= nmi && s >= sc) {
            const float* xr = x + (size_t)row * FF;
            const float* xp = x + (size_t)(row - sc) * FF;
            float d0 = xp[0]     - xr[0];
            float e0 = xp[FF-1]  - xr[FF-1];
            sdd = d0; sde = e0;
            swd = swgt[sc-1] * expf(-fabsf(d0) * exp2f(-(float)sc));
        }
        #pragma unroll
        for (int o = 16; o >= 1; o >>= 1) {
            sdd += __shfl_xor_sync(0xffffffffu, sdd, o);
            sde += __shfl_xor_sync(0xffffffffu, sde, o);
            swd += __shfl_xor_sync(0xffffffffu, swd, o);
        }
        if (tid == 0) { bc[0] = sdd; bc[1] = sde; bc[2] = swd; bc[3] = nmf; }
    }
    __syncthreads();

    float y = projb[tid];
    #pragma unroll
    for (int f = 0; f < FF; f++) y = fmaf(pe_s[f], projW[f*DD + tid], y);

    red[tid] = make_float2(y, y*y);
    __syncthreads();
    for (int o = 128; o >= 1; o >>= 1) {
        if (tid < o) { red[tid].x += red[tid+o].x; red[tid].y += red[tid+o].y; }
        __syncthreads();
    }
    float m = red[0].x * (1.0f/DD);
    float var = fmaxf(red[0].y * (1.0f/DD) - m*m, 0.0f);
    float lny = (y - m) * rsqrtf(var + 1e-5f) * ln2w[tid] + ln2b[tid];
    __syncthreads();

    float e = bc[3]*rpeb[tid] + bc[0]*rpeW[tid] + bc[1]*rpeW[DD + tid] + bc[2]*rpeW[2*DD + tid];
    red[tid] = make_float2(e, e*e);
    __syncthreads();
    for (int o = 128; o >= 1; o >>= 1) {
        if (tid < o) { red[tid].x += red[tid+o].x; red[tid].y += red[tid+o].y; }
        __syncthreads();
    }
    float m2 = red[0].x * (1.0f/DD);
    float var2 = fmaxf(red[0].y * (1.0f/DD) - m2*m2, 0.0f);
    float lne = (e - m2) * rsqrtf(var2 + 1e-5f) * ln1w[tid] + ln1b[tid];

    out[(size_t)row*DD + tid] = lne + lny;
}

// ---------------- launcher ----------------
extern "C" void kernel_launch(void* const* d_in, const int* in_sizes, int n_in,
                              void* d_out, int out_size) {
    const float* x     = (const float*)d_in[0];
    const float* rpeW  = (const float*)d_in[1];
    const float* rpeb  = (const float*)d_in[2];
    const float* projW = (const float*)d_in[3];
    const float* projb = (const float*)d_in[4];
    const float* ln1w  = (const float*)d_in[5];
    const float* ln1b  = (const float*)d_in[6];
    const float* ln2w  = (const float*)d_in[7];
    const float* ln2b  = (const float*)d_in[8];
    const float* alpha = (const float*)d_in[9];
    const float* sigw  = (const float*)d_in[10];
    const float* lns   = (const float*)d_in[11];
    const float* swgt  = (const float*)d_in[12];
    const float* qW    = (const float*)d_in[13];
    const float* qb    = (const float*)d_in[14];
    const float* kW    = (const float*)d_in[15];
    const float* kb    = (const float*)d_in[16];
    float* out = (float*)d_out;

    k_pre     <<<NROW/4, 256>>>(x, qW, qb, kW, kb);
    k_gemm1   <<<dim3(SS/64, SS/64, BB), 256>>>(x);
    k_rowstats<<<NROW, 256>>>();
    k_pe_fused<<<dim3(SS/64, NSPLIT, BB), 256>>>(x, alpha, sigw);
    k_final   <<<NROW, 256>>>(x, rpeW, rpeb, projW, projb,
                              ln1w, ln1b, ln2w, ln2b, lns, swgt, out);
}